// round 5
// baseline (speedup 1.0000x reference)
#include <cuda_runtime.h>
#include <cuda_bf16.h>
#include <cstdint>

// fact_Attention via mma.sync bf16 (sm_103 baseline PTX).
//   energy  = Ehi@Fhi^T + Ehi@Flo^T + Elo@Fhi^T (fp32 accum)
//   weights = softmax(energy, axis=1)
//   outputs = Whi@Fthi^T + Whi@Ftlo^T + Wlo@Fthi^T
// d_out layout: [outputs (N*D) | weights (N*M)]

#define N_ROWS  8192
#define M_FACTS 8192
#define D_DIM   1024

// ---------------- scratch (__device__ globals; no runtime alloc) ----------------
__device__ __align__(1024) __nv_bfloat16 g_Ehi[(size_t)N_ROWS * D_DIM];
__device__ __align__(1024) __nv_bfloat16 g_Elo[(size_t)N_ROWS * D_DIM];
__device__ __align__(1024) __nv_bfloat16 g_Fhi[(size_t)M_FACTS * D_DIM];
__device__ __align__(1024) __nv_bfloat16 g_Flo[(size_t)M_FACTS * D_DIM];
__device__ __align__(1024) __nv_bfloat16 g_Fthi[(size_t)D_DIM * M_FACTS];
__device__ __align__(1024) __nv_bfloat16 g_Ftlo[(size_t)D_DIM * M_FACTS];
__device__ __align__(1024) __nv_bfloat16 g_Whi[(size_t)N_ROWS * M_FACTS];
__device__ __align__(1024) __nv_bfloat16 g_Wlo[(size_t)N_ROWS * M_FACTS];

// ---------------- PTX helpers ----------------
__device__ __forceinline__ uint32_t smem_u32(const void* p) {
    uint32_t a;
    asm("{ .reg .u64 t; cvta.to.shared.u64 t, %1; cvt.u32.u64 %0, t; }" : "=r"(a) : "l"(p));
    return a;
}
__device__ __forceinline__ void cp16(uint32_t s, const void* g) {
    asm volatile("cp.async.cg.shared.global [%0], [%1], 16;" :: "r"(s), "l"(g));
}
#define CP_COMMIT() asm volatile("cp.async.commit_group;" ::: "memory")
#define CP_WAIT1()  asm volatile("cp.async.wait_group 1;" ::: "memory")
#define CP_WAIT0()  asm volatile("cp.async.wait_group 0;" ::: "memory")

__device__ __forceinline__ void ldsm4(uint32_t& r0, uint32_t& r1, uint32_t& r2, uint32_t& r3, uint32_t a) {
    asm volatile("ldmatrix.sync.aligned.m8n8.x4.shared.b16 {%0,%1,%2,%3}, [%4];"
                 : "=r"(r0), "=r"(r1), "=r"(r2), "=r"(r3) : "r"(a));
}
__device__ __forceinline__ void mma16816(float* c, const uint32_t* a, uint32_t b0, uint32_t b1) {
    asm volatile("mma.sync.aligned.m16n8k16.row.col.f32.bf16.bf16.f32 "
                 "{%0,%1,%2,%3}, {%4,%5,%6,%7}, {%8,%9}, {%0,%1,%2,%3};"
                 : "+f"(c[0]), "+f"(c[1]), "+f"(c[2]), "+f"(c[3])
                 : "r"(a[0]), "r"(a[1]), "r"(a[2]), "r"(a[3]), "r"(b0), "r"(b1));
}

// ---------------- 3-region split GEMM: C = sum_r A_r[MR,Kreg] * B_r[NC,Kreg]^T ----------------
// Tile 128x128x64, 256 threads, 8 warps (4m x 2n), warp tile 32x64, 3-stage cp.async, 2 CTAs/SM.
#define NSTG 3
#define STG_BYTES 32768              // A 16KB + B 16KB per stage
#define GEMM_SMEM (NSTG * STG_BYTES)

__global__ __launch_bounds__(256, 2)
void gemm3_mma(const __nv_bfloat16* __restrict__ A0, const __nv_bfloat16* __restrict__ A1,
               const __nv_bfloat16* __restrict__ A2,
               const __nv_bfloat16* __restrict__ B0, const __nv_bfloat16* __restrict__ B1,
               const __nv_bfloat16* __restrict__ B2,
               int Kreg, float* __restrict__ C, int ldc)
{
    extern __shared__ char smem[];
    const uint32_t sbase = smem_u32(smem);
    const int tid = threadIdx.x;
    const int wid = tid >> 5;
    const int lid = tid & 31;
    const int warp_m = wid >> 1;          // 0..3
    const int warp_n = wid & 1;           // 0..1
    const int rowBase = blockIdx.y * 128;
    const int colBase = blockIdx.x * 128;

    const __nv_bfloat16* Aptr[3] = {A0, A1, A2};
    const __nv_bfloat16* Bptr[3] = {B0, B1, B2};

    const int regChunks = Kreg >> 6;      // 64-k chunks per region
    const int NK = 3 * regChunks;

    // ---- load mapping: 4 A rows + 4 B rows of 16B per thread per stage ----
    const int ldRow0 = tid >> 3;          // 0..31
    const int c16    = tid & 7;           // 16B column
    uint32_t soff[4];
    #pragma unroll
    for (int i = 0; i < 4; i++) {
        int row = ldRow0 + i * 32;
        soff[i] = (uint32_t)row * 128u + 16u * (uint32_t)(c16 ^ (row & 7));
    }

    float acc[2][8][4];
    #pragma unroll
    for (int mt = 0; mt < 2; mt++)
        #pragma unroll
        for (int nt = 0; nt < 8; nt++)
            #pragma unroll
            for (int q = 0; q < 4; q++) acc[mt][nt][q] = 0.0f;

    const int rA   = warp_m * 32 + (lid & 15);    // A row for this lane (mt adds 16)
    const int hi16 = (lid >> 4) << 4;             // k-half select (16B)
    const int rBq  = warp_n * 64 + (lid & 15);    // B row base (p adds 16)

    auto issue_load = [&](int st, int chunk) {
        const int r  = chunk / regChunks;
        const int kl = (chunk - r * regChunks) << 6;
        const uint32_t sa = sbase + st * STG_BYTES;
        const uint32_t sbuf = sa + 16384;
        const __nv_bfloat16* Ar = Aptr[r];
        const __nv_bfloat16* Br = Bptr[r];
        #pragma unroll
        for (int i = 0; i < 4; i++) {
            int row = ldRow0 + i * 32;
            cp16(sa + soff[i],   Ar + (size_t)(rowBase + row) * Kreg + kl + (c16 << 3));
            cp16(sbuf + soff[i], Br + (size_t)(colBase + row) * Kreg + kl + (c16 << 3));
        }
        CP_COMMIT();
    };

    issue_load(0, 0);
    issue_load(1, 1);

    for (int chunk = 0; chunk < NK; chunk++) {
        if (chunk + 1 < NK) CP_WAIT1(); else CP_WAIT0();
        __syncthreads();

        if (chunk + 2 < NK) issue_load((chunk + 2) % NSTG, chunk + 2);

        const int st = chunk % NSTG;
        const uint32_t saA = sbase + st * STG_BYTES;
        const uint32_t saB = saA + 16384;

        #pragma unroll
        for (int k16 = 0; k16 < 4; k16++) {
            const uint32_t cb = (uint32_t)(k16 * 32 + hi16);
            uint32_t a[2][4];
            #pragma unroll
            for (int mt = 0; mt < 2; mt++) {
                int row = rA + mt * 16;
                ldsm4(a[mt][0], a[mt][1], a[mt][2], a[mt][3],
                      saA + (uint32_t)row * 128u + (cb ^ (uint32_t)((row & 7) << 4)));
            }
            #pragma unroll
            for (int p = 0; p < 4; p++) {
                uint32_t b0, b1, b2, b3;
                int row = rBq + p * 16;
                ldsm4(b0, b1, b2, b3,
                      saB + (uint32_t)row * 128u + (cb ^ (uint32_t)((row & 7) << 4)));
                #pragma unroll
                for (int mt = 0; mt < 2; mt++) {
                    mma16816(acc[mt][2 * p + 0], a[mt], b0, b2);
                    mma16816(acc[mt][2 * p + 1], a[mt], b1, b3);
                }
            }
        }
        __syncthreads();
    }

    // ---- epilogue: fp32 direct to C ----
    const int gid = lid >> 2;
    const int tig = lid & 3;
    #pragma unroll
    for (int mt = 0; mt < 2; mt++) {
        const int r0 = rowBase + warp_m * 32 + mt * 16 + gid;
        #pragma unroll
        for (int nt = 0; nt < 8; nt++) {
            const int col = colBase + warp_n * 64 + nt * 8 + tig * 2;
            float2 v0 = make_float2(acc[mt][nt][0], acc[mt][nt][1]);
            float2 v1 = make_float2(acc[mt][nt][2], acc[mt][nt][3]);
            *reinterpret_cast<float2*>(&C[(size_t)r0 * ldc + col]) = v0;
            *reinterpret_cast<float2*>(&C[(size_t)(r0 + 8) * ldc + col]) = v1;
        }
    }
}

// ---------------- split X[R,1024] fp32 -> Xhi, Xlo bf16 ----------------
__global__ __launch_bounds__(256) void split_kernel(
    const float* __restrict__ X, __nv_bfloat16* __restrict__ XH, __nv_bfloat16* __restrict__ XL)
{
    const size_t e = ((size_t)blockIdx.x * 256 + threadIdx.x) * 4;
    float4 v = *reinterpret_cast<const float4*>(X + e);
    float xs[4] = {v.x, v.y, v.z, v.w};
    unsigned short hs[4], ls[4];
    #pragma unroll
    for (int i = 0; i < 4; i++) {
        __nv_bfloat16 h = __float2bfloat16(xs[i]);
        __nv_bfloat16 l = __float2bfloat16(xs[i] - __bfloat162float(h));
        hs[i] = __bfloat16_as_ushort(h);
        ls[i] = __bfloat16_as_ushort(l);
    }
    uint2 hp, lp;
    hp.x = (uint32_t)hs[0] | ((uint32_t)hs[1] << 16);
    hp.y = (uint32_t)hs[2] | ((uint32_t)hs[3] << 16);
    lp.x = (uint32_t)ls[0] | ((uint32_t)ls[1] << 16);
    lp.y = (uint32_t)ls[2] | ((uint32_t)ls[3] << 16);
    *reinterpret_cast<uint2*>(XH + e) = hp;
    *reinterpret_cast<uint2*>(XL + e) = lp;
}

// ---------------- transpose+split F[8192,1024] -> Fthi/Ftlo [1024, 8192] ----------------
__global__ __launch_bounds__(256) void transpose_split_kernel(const float* __restrict__ F)
{
    __shared__ float tile[32][33];
    const int m0 = blockIdx.x * 32;
    const int d0 = blockIdx.y * 32;
    const int tx = threadIdx.x;      // 0..31
    const int ty = threadIdx.y;      // 0..7
    #pragma unroll
    for (int j = ty; j < 32; j += 8)
        tile[j][tx] = F[(size_t)(m0 + j) * D_DIM + d0 + tx];
    __syncthreads();
    #pragma unroll
    for (int j = ty; j < 32; j += 8) {
        const int d = d0 + j;
        const int m = m0 + tx;
        float x = tile[tx][j];
        __nv_bfloat16 h = __float2bfloat16(x);
        __nv_bfloat16 l = __float2bfloat16(x - __bfloat162float(h));
        g_Fthi[(size_t)d * M_FACTS + m] = h;
        g_Ftlo[(size_t)d * M_FACTS + m] = l;
    }
}

// ---------------- softmax rows in place + emit Whi/Wlo ----------------
__global__ __launch_bounds__(256) void softmax_split_kernel(float* __restrict__ W)
{
    __shared__ float buf[M_FACTS];   // 32 KB
    __shared__ float red[256];

    const int row = blockIdx.x;
    const int tid = threadIdx.x;
    float* p = W + (size_t)row * M_FACTS;
    __nv_bfloat16* wh = g_Whi + (size_t)row * M_FACTS;
    __nv_bfloat16* wl = g_Wlo + (size_t)row * M_FACTS;

    float lmax = -3.402823466e+38f;
    for (int i = tid; i < M_FACTS; i += 256) {
        float v = p[i];
        buf[i] = v;
        lmax = fmaxf(lmax, v);
    }
    red[tid] = lmax;
    __syncthreads();
    #pragma unroll
    for (int s = 128; s > 0; s >>= 1) {
        if (tid < s) red[tid] = fmaxf(red[tid], red[tid + s]);
        __syncthreads();
    }
    const float mx = red[0];
    __syncthreads();

    float lsum = 0.0f;
    for (int i = tid; i < M_FACTS; i += 256) {
        float e = expf(buf[i] - mx);
        buf[i] = e;
        lsum += e;
    }
    red[tid] = lsum;
    __syncthreads();
    #pragma unroll
    for (int s = 128; s > 0; s >>= 1) {
        if (tid < s) red[tid] += red[tid + s];
        __syncthreads();
    }
    const float inv = 1.0f / red[0];
    __syncthreads();

    for (int i = tid; i < M_FACTS; i += 256) {
        float w = buf[i] * inv;
        p[i] = w;
        __nv_bfloat16 h = __float2bfloat16(w);
        __nv_bfloat16 l = __float2bfloat16(w - __bfloat162float(h));
        wh[i] = h;
        wl[i] = l;
    }
}

// ---------------- launch ----------------
extern "C" void kernel_launch(void* const* d_in, const int* in_sizes, int n_in,
                              void* d_out, int out_size)
{
    const float* E = (const float*)d_in[0];   // [N, D]
    const float* F = (const float*)d_in[1];   // [M, D]
    float* outputs = (float*)d_out;                               // [N, D]
    float* weights = (float*)d_out + (size_t)N_ROWS * D_DIM;      // [N, M]

    cudaFuncSetAttribute(gemm3_mma, cudaFuncAttributeMaxDynamicSharedMemorySize, GEMM_SMEM);

    __nv_bfloat16 *Ehi, *Elo, *Fhi, *Flo, *Fthi, *Ftlo, *Whi, *Wlo;
    cudaGetSymbolAddress((void**)&Ehi, g_Ehi);
    cudaGetSymbolAddress((void**)&Elo, g_Elo);
    cudaGetSymbolAddress((void**)&Fhi, g_Fhi);
    cudaGetSymbolAddress((void**)&Flo, g_Flo);
    cudaGetSymbolAddress((void**)&Fthi, g_Fthi);
    cudaGetSymbolAddress((void**)&Ftlo, g_Ftlo);
    cudaGetSymbolAddress((void**)&Whi, g_Whi);
    cudaGetSymbolAddress((void**)&Wlo, g_Wlo);

    // 1) splits
    split_kernel<<<(N_ROWS * D_DIM) / (256 * 4), 256>>>(E, Ehi, Elo);
    split_kernel<<<(M_FACTS * D_DIM) / (256 * 4), 256>>>(F, Fhi, Flo);
    transpose_split_kernel<<<dim3(M_FACTS / 32, D_DIM / 32), dim3(32, 8)>>>(F);

    // 2) energy = Ehi@Fhi^T + Ehi@Flo^T + Elo@Fhi^T -> weights buffer (raw logits)
    gemm3_mma<<<dim3(M_FACTS / 128, N_ROWS / 128), 256, GEMM_SMEM>>>(
        Ehi, Ehi, Elo, Fhi, Flo, Fhi, D_DIM, weights, M_FACTS);

    // 3) softmax in place + split W
    softmax_split_kernel<<<N_ROWS, 256>>>(weights);

    // 4) outputs = Whi@Fthi^T + Whi@Ftlo^T + Wlo@Fthi^T
    gemm3_mma<<<dim3(D_DIM / 128, N_ROWS / 128), 256, GEMM_SMEM>>>(
        Whi, Whi, Wlo, Fthi, Ftlo, Fthi, M_FACTS, outputs, D_DIM);
}

// round 9
// speedup vs baseline: 1.5734x; 1.5734x over previous
#include <cuda_runtime.h>
#include <cuda_bf16.h>
#include <cstdint>

// fact_Attention via mma.sync bf16, fused two-term split (single pass):
//   C = Ahi@Bhi^T + Ahi@Blo^T + Alo@Bhi^T, fp32 accum.
// energy = split(E) x split(F); weights = softmax(energy); outputs = split(W) x split(F^T)
// d_out layout: [outputs (N*D) | weights (N*M)]

#define N_ROWS  8192
#define M_FACTS 8192
#define D_DIM   1024

// ---------------- scratch (__device__ globals; no runtime alloc) ----------------
__device__ __align__(1024) __nv_bfloat16 g_Ehi[(size_t)N_ROWS * D_DIM];
__device__ __align__(1024) __nv_bfloat16 g_Elo[(size_t)N_ROWS * D_DIM];
__device__ __align__(1024) __nv_bfloat16 g_Fhi[(size_t)M_FACTS * D_DIM];
__device__ __align__(1024) __nv_bfloat16 g_Flo[(size_t)M_FACTS * D_DIM];
__device__ __align__(1024) __nv_bfloat16 g_Fthi[(size_t)D_DIM * M_FACTS];
__device__ __align__(1024) __nv_bfloat16 g_Ftlo[(size_t)D_DIM * M_FACTS];
__device__ __align__(1024) __nv_bfloat16 g_Whi[(size_t)N_ROWS * M_FACTS];
__device__ __align__(1024) __nv_bfloat16 g_Wlo[(size_t)N_ROWS * M_FACTS];

// ---------------- PTX helpers ----------------
__device__ __forceinline__ uint32_t smem_u32(const void* p) {
    uint32_t a;
    asm("{ .reg .u64 t; cvta.to.shared.u64 t, %1; cvt.u32.u64 %0, t; }" : "=r"(a) : "l"(p));
    return a;
}
__device__ __forceinline__ void cp16(uint32_t s, const void* g) {
    asm volatile("cp.async.cg.shared.global [%0], [%1], 16;" :: "r"(s), "l"(g));
}
#define CP_COMMIT() asm volatile("cp.async.commit_group;" ::: "memory")
#define CP_WAIT0()  asm volatile("cp.async.wait_group 0;" ::: "memory")

__device__ __forceinline__ void ldsm4(uint32_t& r0, uint32_t& r1, uint32_t& r2, uint32_t& r3, uint32_t a) {
    asm volatile("ldmatrix.sync.aligned.m8n8.x4.shared.b16 {%0,%1,%2,%3}, [%4];"
                 : "=r"(r0), "=r"(r1), "=r"(r2), "=r"(r3) : "r"(a));
}
__device__ __forceinline__ void mma16816(float* c, const uint32_t* a, uint32_t b0, uint32_t b1) {
    asm volatile("mma.sync.aligned.m16n8k16.row.col.f32.bf16.bf16.f32 "
                 "{%0,%1,%2,%3}, {%4,%5,%6,%7}, {%8,%9}, {%0,%1,%2,%3};"
                 : "+f"(c[0]), "+f"(c[1]), "+f"(c[2]), "+f"(c[3])
                 : "r"(a[0]), "r"(a[1]), "r"(a[2]), "r"(a[3]), "r"(b0), "r"(b1));
}

// ---------------- fused split GEMM ----------------
// Tile 128x128, K-chunk 64, 256 threads, 8 warps (4m x 2n), warp tile 32x64.
// Stage (64KB): AH(16K) AL(16K) BH(16K) BL(16K); 2 stages = 128KB, 1 CTA/SM.
// 128B rows, swizzle: 16B unit c' = c ^ (row & 7)   (R4-proven layout).
#define STG_BYTES 65536
#define GEMM_SMEM (2 * STG_BYTES)

__global__ __launch_bounds__(256)
void gemm_fused_mma(const __nv_bfloat16* __restrict__ AH, const __nv_bfloat16* __restrict__ AL,
                    const __nv_bfloat16* __restrict__ BH, const __nv_bfloat16* __restrict__ BL,
                    int Kreg, float* __restrict__ C, int ldc)
{
    extern __shared__ char smem[];
    const uint32_t sbase = smem_u32(smem);
    const int tid = threadIdx.x;
    const int wid = tid >> 5;
    const int lid = tid & 31;
    const int warp_m = wid >> 1;
    const int warp_n = wid & 1;
    const int rowBase = blockIdx.y * 128;
    const int colBase = blockIdx.x * 128;

    // ---- cp.async mapping (R4-proven): 8 threads per 128B row, 4 row-groups ----
    const int ldRow0 = tid >> 3;          // 0..31
    const int c16    = tid & 7;           // 16B unit in row
    uint32_t soff[4];
    #pragma unroll
    for (int i = 0; i < 4; i++) {
        int row = ldRow0 + i * 32;
        soff[i] = (uint32_t)row * 128u + 16u * (uint32_t)(c16 ^ (row & 7));
    }

    float acc[2][8][4];
    #pragma unroll
    for (int mt = 0; mt < 2; mt++)
        #pragma unroll
        for (int nt = 0; nt < 8; nt++)
            #pragma unroll
            for (int q = 0; q < 4; q++) acc[mt][nt][q] = 0.0f;

    const int rA   = warp_m * 32 + (lid & 15);    // + mt*16
    const int hi16 = (lid >> 4) << 4;
    const int rB   = warp_n * 64 + (lid & 15);    // + p*16

    auto issue_load = [&](int st, int chunk) {
        const int kl = chunk << 6;                 // 64 k-elements per chunk
        const uint32_t b = sbase + st * STG_BYTES;
        #pragma unroll
        for (int i = 0; i < 4; i++) {
            const int row = ldRow0 + i * 32;
            const size_t gar = (size_t)(rowBase + row) * Kreg + kl + (c16 << 3);
            const size_t gbr = (size_t)(colBase + row) * Kreg + kl + (c16 << 3);
            cp16(b          + soff[i], AH + gar);
            cp16(b + 16384u + soff[i], AL + gar);
            cp16(b + 32768u + soff[i], BH + gbr);
            cp16(b + 49152u + soff[i], BL + gbr);
        }
        CP_COMMIT();
    };

    const int NK = Kreg >> 6;
    issue_load(0, 0);

    for (int chunk = 0; chunk < NK; chunk++) {
        CP_WAIT0();
        __syncthreads();                       // also guards buffer reuse across iters
        if (chunk + 1 < NK) issue_load((chunk + 1) & 1, chunk + 1);

        const uint32_t stb = sbase + (chunk & 1) * STG_BYTES;

        #pragma unroll
        for (int k16 = 0; k16 < 4; k16++) {
            const uint32_t cb = (uint32_t)(k16 * 32 + hi16);
            uint32_t aH[2][4], aL[2][4];
            #pragma unroll
            for (int mt = 0; mt < 2; mt++) {
                const int row = rA + mt * 16;
                const uint32_t ra = (uint32_t)row * 128u + (cb ^ (uint32_t)((row & 7) << 4));
                ldsm4(aH[mt][0], aH[mt][1], aH[mt][2], aH[mt][3], stb + ra);
                ldsm4(aL[mt][0], aL[mt][1], aL[mt][2], aL[mt][3], stb + 16384u + ra);
            }
            #pragma unroll
            for (int p = 0; p < 4; p++) {
                const int row = rB + p * 16;
                const uint32_t rb = (uint32_t)row * 128u + (cb ^ (uint32_t)((row & 7) << 4));
                uint32_t h0, h1, h2, h3, l0, l1, l2, l3;
                ldsm4(h0, h1, h2, h3, stb + 32768u + rb);
                ldsm4(l0, l1, l2, l3, stb + 49152u + rb);
                #pragma unroll
                for (int mt = 0; mt < 2; mt++) {
                    mma16816(acc[mt][2 * p + 0], aH[mt], h0, h2);   // hh
                    mma16816(acc[mt][2 * p + 1], aH[mt], h1, h3);
                    mma16816(acc[mt][2 * p + 0], aH[mt], l0, l2);   // hl
                    mma16816(acc[mt][2 * p + 1], aH[mt], l1, l3);
                    mma16816(acc[mt][2 * p + 0], aL[mt], h0, h2);   // lh
                    mma16816(acc[mt][2 * p + 1], aL[mt], h1, h3);
                }
            }
        }
    }

    // ---- epilogue: fp32 direct to C ----
    const int gid = lid >> 2;
    const int tig = lid & 3;
    #pragma unroll
    for (int mt = 0; mt < 2; mt++) {
        const int r0 = rowBase + warp_m * 32 + mt * 16 + gid;
        #pragma unroll
        for (int nt = 0; nt < 8; nt++) {
            const int col = colBase + warp_n * 64 + nt * 8 + tig * 2;
            float2 v0 = make_float2(acc[mt][nt][0], acc[mt][nt][1]);
            float2 v1 = make_float2(acc[mt][nt][2], acc[mt][nt][3]);
            *reinterpret_cast<float2*>(&C[(size_t)r0 * ldc + col]) = v0;
            *reinterpret_cast<float2*>(&C[(size_t)(r0 + 8) * ldc + col]) = v1;
        }
    }
}

// ---------------- split X[R,1024] fp32 -> Xhi, Xlo bf16 ----------------
__global__ __launch_bounds__(256) void split_kernel(
    const float* __restrict__ X, __nv_bfloat16* __restrict__ XH, __nv_bfloat16* __restrict__ XL)
{
    const size_t e = ((size_t)blockIdx.x * 256 + threadIdx.x) * 4;
    float4 v = *reinterpret_cast<const float4*>(X + e);
    float xs[4] = {v.x, v.y, v.z, v.w};
    unsigned short hs[4], ls[4];
    #pragma unroll
    for (int i = 0; i < 4; i++) {
        __nv_bfloat16 h = __float2bfloat16(xs[i]);
        __nv_bfloat16 l = __float2bfloat16(xs[i] - __bfloat162float(h));
        hs[i] = __bfloat16_as_ushort(h);
        ls[i] = __bfloat16_as_ushort(l);
    }
    uint2 hp, lp;
    hp.x = (uint32_t)hs[0] | ((uint32_t)hs[1] << 16);
    hp.y = (uint32_t)hs[2] | ((uint32_t)hs[3] << 16);
    lp.x = (uint32_t)ls[0] | ((uint32_t)ls[1] << 16);
    lp.y = (uint32_t)ls[2] | ((uint32_t)ls[3] << 16);
    *reinterpret_cast<uint2*>(XH + e) = hp;
    *reinterpret_cast<uint2*>(XL + e) = lp;
}

// ---------------- transpose+split F[8192,1024] -> Fthi/Ftlo [1024, 8192] ----------------
__global__ __launch_bounds__(256) void transpose_split_kernel(const float* __restrict__ F)
{
    __shared__ float tile[32][33];
    const int m0 = blockIdx.x * 32;
    const int d0 = blockIdx.y * 32;
    const int tx = threadIdx.x;
    const int ty = threadIdx.y;
    #pragma unroll
    for (int j = ty; j < 32; j += 8)
        tile[j][tx] = F[(size_t)(m0 + j) * D_DIM + d0 + tx];
    __syncthreads();
    #pragma unroll
    for (int j = ty; j < 32; j += 8) {
        const int d = d0 + j;
        const int m = m0 + tx;
        float x = tile[tx][j];
        __nv_bfloat16 h = __float2bfloat16(x);
        __nv_bfloat16 l = __float2bfloat16(x - __bfloat162float(h));
        g_Fthi[(size_t)d * M_FACTS + m] = h;
        g_Ftlo[(size_t)d * M_FACTS + m] = l;
    }
}

// ---------------- softmax rows in place + emit Whi/Wlo ----------------
__global__ __launch_bounds__(256) void softmax_split_kernel(float* __restrict__ W)
{
    __shared__ float buf[M_FACTS];
    __shared__ float red[256];

    const int row = blockIdx.x;
    const int tid = threadIdx.x;
    float* p = W + (size_t)row * M_FACTS;
    __nv_bfloat16* wh = g_Whi + (size_t)row * M_FACTS;
    __nv_bfloat16* wl = g_Wlo + (size_t)row * M_FACTS;

    float lmax = -3.402823466e+38f;
    for (int i = tid; i < M_FACTS; i += 256) {
        float v = p[i];
        buf[i] = v;
        lmax = fmaxf(lmax, v);
    }
    red[tid] = lmax;
    __syncthreads();
    #pragma unroll
    for (int s = 128; s > 0; s >>= 1) {
        if (tid < s) red[tid] = fmaxf(red[tid], red[tid + s]);
        __syncthreads();
    }
    const float mx = red[0];
    __syncthreads();

    float lsum = 0.0f;
    for (int i = tid; i < M_FACTS; i += 256) {
        float e = expf(buf[i] - mx);
        buf[i] = e;
        lsum += e;
    }
    red[tid] = lsum;
    __syncthreads();
    #pragma unroll
    for (int s = 128; s > 0; s >>= 1) {
        if (tid < s) red[tid] += red[tid + s];
        __syncthreads();
    }
    const float inv = 1.0f / red[0];
    __syncthreads();

    for (int i = tid; i < M_FACTS; i += 256) {
        float w = buf[i] * inv;
        p[i] = w;
        __nv_bfloat16 h = __float2bfloat16(w);
        __nv_bfloat16 l = __float2bfloat16(w - __bfloat162float(h));
        wh[i] = h;
        wl[i] = l;
    }
}

// ---------------- launch ----------------
extern "C" void kernel_launch(void* const* d_in, const int* in_sizes, int n_in,
                              void* d_out, int out_size)
{
    const float* E = (const float*)d_in[0];   // [N, D]
    const float* F = (const float*)d_in[1];   // [M, D]
    float* outputs = (float*)d_out;                               // [N, D]
    float* weights = (float*)d_out + (size_t)N_ROWS * D_DIM;      // [N, M]

    cudaFuncSetAttribute(gemm_fused_mma, cudaFuncAttributeMaxDynamicSharedMemorySize, GEMM_SMEM);

    __nv_bfloat16 *Ehi, *Elo, *Fhi, *Flo, *Fthi, *Ftlo, *Whi, *Wlo;
    cudaGetSymbolAddress((void**)&Ehi, g_Ehi);
    cudaGetSymbolAddress((void**)&Elo, g_Elo);
    cudaGetSymbolAddress((void**)&Fhi, g_Fhi);
    cudaGetSymbolAddress((void**)&Flo, g_Flo);
    cudaGetSymbolAddress((void**)&Fthi, g_Fthi);
    cudaGetSymbolAddress((void**)&Ftlo, g_Ftlo);
    cudaGetSymbolAddress((void**)&Whi, g_Whi);
    cudaGetSymbolAddress((void**)&Wlo, g_Wlo);

    // 1) splits
    split_kernel<<<(N_ROWS * D_DIM) / (256 * 4), 256>>>(E, Ehi, Elo);
    split_kernel<<<(M_FACTS * D_DIM) / (256 * 4), 256>>>(F, Fhi, Flo);
    transpose_split_kernel<<<dim3(M_FACTS / 32, D_DIM / 32), dim3(32, 8)>>>(F);

    // 2) energy (fused hh+hl+lh) -> weights buffer (raw logits)
    gemm_fused_mma<<<dim3(M_FACTS / 128, N_ROWS / 128), 256, GEMM_SMEM>>>(
        Ehi, Elo, Fhi, Flo, D_DIM, weights, M_FACTS);

    // 3) softmax in place + split W
    softmax_split_kernel<<<N_ROWS, 256>>>(weights);

    // 4) outputs = W @ F (fused)
    gemm_fused_mma<<<dim3(D_DIM / 128, N_ROWS / 128), 256, GEMM_SMEM>>>(
        Whi, Wlo, Fthi, Ftlo, M_FACTS, outputs, D_DIM);
}